// round 9
// baseline (speedup 1.0000x reference)
#include <cuda_runtime.h>
#include <math.h>

#define B 32
#define H 512
#define W 512
#define C4 (W / 4)
#define KS 31
#define PAD 15
#define IMG4 (H * C4)
#define STRIPS 32
#define ROWS (H / STRIPS)      // 16
#define ROUNDS (ROWS / 2)      // 8
#define NBLOCKS (B * STRIPS)   // 1024

__device__ float g_part[NBLOCKS * 4];
__device__ unsigned int g_ctr;

typedef unsigned long long u64;

__inline__ __device__ u64 pk2(float lo, float hi) {
    u64 r; asm("mov.b64 %0,{%1,%2};" : "=l"(r) : "f"(lo), "f"(hi)); return r;
}
__inline__ __device__ void upk2(u64 v, float& a, float& b) {
    asm("mov.b64 {%0,%1},%2;" : "=f"(a), "=f"(b) : "l"(v));
}
__inline__ __device__ u64 add2(u64 a, u64 b) {
    u64 d; asm("add.rn.f32x2 %0,%1,%2;" : "=l"(d) : "l"(a), "l"(b)); return d;
}
__inline__ __device__ u64 mul2(u64 a, u64 b) {
    u64 d; asm("mul.rn.f32x2 %0,%1,%2;" : "=l"(d) : "l"(a), "l"(b)); return d;
}
__inline__ __device__ u64 fma2_(u64 a, u64 b, u64 c) {
    u64 d; asm("fma.rn.f32x2 %0,%1,%2,%3;" : "=l"(d) : "l"(a), "l"(b), "l"(c)); return d;
}

__inline__ __device__ float warp_reduce(float v) {
    #pragma unroll
    for (int o = 16; o > 0; o >>= 1) v += __shfl_down_sync(0xffffffffu, v, o);
    return v;
}

__inline__ __device__ void warp_iscan2(float& a, float& b, int lane) {
    #pragma unroll
    for (int o = 1; o < 32; o <<= 1) {
        const float na = __shfl_up_sync(0xffffffffu, a, o);
        const float nb = __shfl_up_sync(0xffffffffu, b, o);
        if (lane >= o) { a += na; b += nb; }
    }
}

__inline__ __device__ float4 f4add(float4 a, float4 b) {
    return make_float4(a.x + b.x, a.y + b.y, a.z + b.z, a.w + b.w);
}
__inline__ __device__ float4 f4sub(float4 a, float4 b) {
    return make_float4(a.x - b.x, a.y - b.y, a.z - b.z, a.w - b.w);
}

__global__ void __launch_bounds__(128, 7)
fused_loss_kernel(const float4* __restrict__ pred,
                  const float4* __restrict__ target,
                  float* __restrict__ out) {
    const int strip = blockIdx.x;
    const int b     = blockIdx.y;
    const int w     = threadIdx.x;
    const int lane  = w & 31;
    const int wid   = w >> 5;
    const int r0    = strip * ROWS;

    const float4* t = target + b * IMG4;
    const float4* p = pred   + b * IMG4;

    __shared__ float4 sP[2][2][136];
    __shared__ float2 s_warp[2][4];
    __shared__ float  s_red[4][4];

    if (w < 16) sP[(w >> 3) & 1][(w >> 2) & 1][w & 3] = make_float4(0.f, 0.f, 0.f, 0.f);

    const float4 zero4 = make_float4(0.f, 0.f, 0.f, 0.f);

    // preamble vertical window with 2-way ILP
    float4 sA = zero4, sB = zero4;
    {
        int hlo = r0 - PAD; if (hlo < 0) hlo = 0;
        int hhi = r0 + PAD; if (hhi > H) hhi = H;
        int h = hlo;
        for (; h + 1 < hhi; h += 2) {
            sA = f4add(sA, t[h * C4 + w]);
            sB = f4add(sB, t[(h + 1) * C4 + w]);
        }
        if (h < hhi) sA = f4add(sA, t[h * C4 + w]);
    }
    float4 sum4 = f4add(sA, sB);

    const float invf = 1.0f / (KS * KS);
    const u64 INV2 = pk2(invf, invf);
    const u64 NEG1 = pk2(-1.f, -1.f);
    u64 acc0 = 0ull, acc1 = 0ull, acc2 = 0ull, acc3 = 0ull;

    // round-0 vertical-window loads
    float4 ca0 = (r0 + PAD < H)      ? t[(r0 + PAD) * C4 + w]       : zero4;
    float4 ca1 = (r0 + 1 + PAD < H)  ? t[(r0 + 1 + PAD) * C4 + w]   : zero4;
    float4 cs0 = (r0 - PAD >= 0)     ? t[(r0 - PAD) * C4 + w]       : zero4;
    float4 cs1 = (r0 + 1 - PAD >= 0) ? t[(r0 + 1 - PAD) * C4 + w]   : zero4;

    for (int g = 0; g < ROUNDS; ++g) {
        const int r   = r0 + 2 * g;
        const int buf = g & 1;

        // vertical sums (consume current loads)
        sum4 = f4add(sum4, ca0);
        const float4 vs0 = sum4;
        sum4 = f4sub(sum4, cs0);
        sum4 = f4add(sum4, ca1);
        const float4 vs1 = sum4;
        sum4 = f4sub(sum4, cs1);

        // prefetch next round's vertical-window loads (hidden by scan+barriers)
        const int rn = r + 2;
        float4 na0 = zero4, na1 = zero4, ns0 = zero4, ns1 = zero4;
        if (g + 1 < ROUNDS) {
            na0 = (rn + PAD < H)     ? t[(rn + PAD) * C4 + w]     : zero4;
            na1 = (rn + 1 + PAD < H) ? t[(rn + 1 + PAD) * C4 + w] : zero4;
            ns0 = t[(rn - PAD) * C4 + w];       // rn-PAD >= r0+1-13 >= 0 for rn>=PAD; guard:
            if (rn - PAD < 0) ns0 = zero4;
            ns1 = (rn + 1 - PAD >= 0) ? t[(rn + 1 - PAD) * C4 + w] : zero4;
        }

        // thread-local prefixes
        const float q0a = vs0.x, q1a = q0a + vs0.y, q2a = q1a + vs0.z, q3a = q2a + vs0.w;
        const float q0b = vs1.x, q1b = q0b + vs1.y, q2b = q1b + vs1.z, q3b = q2b + vs1.w;

        float ia = q3a, ib = q3b;
        warp_iscan2(ia, ib, lane);
        const float exa = ia - q3a;
        const float exb = ib - q3b;
        if (lane == 31) s_warp[buf][wid] = make_float2(ia, ib);
        __syncthreads();

        // tg/x loads land during base-compute + barrier2
        const float4 tg0 = t[r * C4 + w];
        const float4 tg1 = t[(r + 1) * C4 + w];
        const float4 x0  = p[r * C4 + w];
        const float4 x1  = p[(r + 1) * C4 + w];

        const float2 W0 = s_warp[buf][0];
        const float2 W1 = s_warp[buf][1];
        const float2 W2 = s_warp[buf][2];
        const float2 W3 = s_warp[buf][3];

        const float offa = (wid > 0 ? W0.x : 0.f) + (wid > 1 ? W1.x : 0.f) + (wid > 2 ? W2.x : 0.f);
        const float offb = (wid > 0 ? W0.y : 0.f) + (wid > 1 ? W1.y : 0.f) + (wid > 2 ? W2.y : 0.f);
        const float basea = offa + exa;
        const float baseb = offb + exb;

        sP[buf][0][w + 4] = make_float4(basea + q0a, basea + q1a, basea + q2a, basea + q3a);
        sP[buf][1][w + 4] = make_float4(baseb + q0b, baseb + q1b, baseb + q2b, baseb + q3b);
        if (w < 4) {
            const float tota = W0.x + W1.x + W2.x + W3.x;
            const float totb = W0.y + W1.y + W2.y + W3.y;
            sP[buf][0][132 + w] = make_float4(tota, tota, tota, tota);
            sP[buf][1][132 + w] = make_float4(totb, totb, totb, totb);
        }
        __syncthreads();

        #pragma unroll
        for (int j = 0; j < 2; ++j) {
            const float4 lo = sP[buf][j][w];
            const float4 A  = sP[buf][j][w + 7];
            const float4 Bv = sP[buf][j][w + 8];
            const float4 tg = j ? tg1 : tg0;
            const float4 xq = j ? x1 : x0;

            const float hi[4] = {A.w, Bv.x, Bv.y, Bv.z};
            const float lov[4] = {lo.x, lo.y, lo.z, lo.w};
            const float tgv[4] = {tg.x, tg.y, tg.z, tg.w};
            const float xv[4]  = {xq.x, xq.y, xq.z, xq.w};

            #pragma unroll
            for (int m = 0; m < 2; ++m) {
                const int k = 2 * m;
                const u64 hi2 = pk2(hi[k], hi[k + 1]);
                const u64 lo2 = pk2(lov[k], lov[k + 1]);
                const u64 tg2 = pk2(tgv[k], tgv[k + 1]);
                const u64 x2  = pk2(xv[k], xv[k + 1]);

                const u64 box2 = mul2(fma2_(lo2, NEG1, hi2), INV2);  // (hi-lo)/961
                const u64 d2   = fma2_(tg2, NEG1, box2);             // box - tg
                float da, db; upk2(d2, da, db);
                const float weita = fmaf(5.f, fabsf(da), 1.f);
                const float weitb = fmaf(5.f, fabsf(db), 1.f);

                // scalar exp/log/sigmoid per component
                const float ea = __expf(-fabsf(xv[k]));
                const float eb = __expf(-fabsf(xv[k + 1]));
                const float lga = __logf(1.f + ea);
                const float lgb = __logf(1.f + eb);
                const float iva = __fdividef(1.f, 1.f + ea);
                const float ivb = __fdividef(1.f, 1.f + eb);
                const float pa = (xv[k] >= 0.f) ? iva : 1.f - iva;
                const float pb = (xv[k + 1] >= 0.f) ? ivb : 1.f - ivb;

                const u64 w2   = pk2(weita, weitb);
                const u64 mlg2 = pk2(fmaxf(xv[k], 0.f) + lga, fmaxf(xv[k + 1], 0.f) + lgb);
                const u64 xt2  = mul2(x2, tg2);
                const u64 bce2 = fma2_(xt2, NEG1, mlg2);             // max+lg - x*tg
                const u64 p2   = pk2(pa, pb);

                acc0 = add2(acc0, w2);
                acc1 = fma2_(w2, bce2, acc1);
                acc2 = fma2_(mul2(p2, tg2), w2, acc2);
                acc3 = fma2_(add2(p2, tg2), w2, acc3);
            }
        }

        ca0 = na0; ca1 = na1; cs0 = ns0; cs1 = ns1;
    }

    // unpack accumulators
    float a0x, a0y, a1x, a1y, a2x, a2y, a3x, a3y;
    upk2(acc0, a0x, a0y); upk2(acc1, a1x, a1y);
    upk2(acc2, a2x, a2y); upk2(acc3, a3x, a3y);
    float vals[4] = {a0x + a0y, a1x + a1y, a2x + a2y, a3x + a3y};

    #pragma unroll
    for (int k = 0; k < 4; ++k) {
        const float v = warp_reduce(vals[k]);
        if (lane == 0) s_red[k][wid] = v;
    }
    __syncthreads();

    if (wid == 0) {
        float v[4];
        #pragma unroll
        for (int k = 0; k < 4; ++k) {
            float vv = (lane < 4) ? s_red[k][lane] : 0.f;
            #pragma unroll
            for (int o = 2; o > 0; o >>= 1) vv += __shfl_down_sync(0xffffffffu, vv, o);
            v[k] = vv;
        }
        if (lane == 0) {
            #pragma unroll
            for (int k = 0; k < 4; ++k)
                g_part[(b * STRIPS + strip) * 4 + k] = v[k];
            __threadfence();
        }
        __syncwarp();

        unsigned int ticket = 0;
        if (lane == 0) ticket = atomicAdd(&g_ctr, 1u);
        ticket = __shfl_sync(0xffffffffu, ticket, 0);
        if (ticket == NBLOCKS - 1) {
            float wsum = 0.f, wbce_n = 0.f, inter = 0.f, uni = 0.f;
            #pragma unroll 4
            for (int s = 0; s < STRIPS; ++s) {
                const float* pp = &g_part[(lane * STRIPS + s) * 4];
                wsum   += pp[0];
                wbce_n += pp[1];
                inter  += pp[2];
                uni    += pp[3];
            }
            const float wbce = wbce_n / wsum;
            const float wiou = 1.0f - (inter + 1.0f) / (uni - inter + 1.0f);
            float loss = warp_reduce(wbce + wiou);
            if (lane == 0) {
                out[0] = loss * (1.0f / B);
                g_ctr = 0;
            }
        }
    }
}

extern "C" void kernel_launch(void* const* d_in, const int* in_sizes, int n_in,
                              void* d_out, int out_size) {
    const float4* pred   = (const float4*)d_in[0];
    const float4* target = (const float4*)d_in[1];
    float* out = (float*)d_out;

    dim3 grid(STRIPS, B);
    fused_loss_kernel<<<grid, 128>>>(pred, target, out);
}

// round 10
// speedup vs baseline: 1.1023x; 1.1023x over previous
#include <cuda_runtime.h>
#include <math.h>

#define B 32
#define H 512
#define W 512
#define C4 (W / 4)
#define KS 31
#define PAD 15
#define IMG4 (H * C4)
#define STRIPS 32
#define ROWS (H / STRIPS)      // 16
#define ROUNDS (ROWS / 2)      // 8
#define NBLOCKS (B * STRIPS)   // 1024

__device__ float g_part[NBLOCKS * 4];
__device__ unsigned int g_ctr;

__inline__ __device__ float warp_reduce(float v) {
    #pragma unroll
    for (int o = 16; o > 0; o >>= 1) v += __shfl_down_sync(0xffffffffu, v, o);
    return v;
}

__inline__ __device__ void warp_iscan2(float& a, float& b, int lane) {
    #pragma unroll
    for (int o = 1; o < 32; o <<= 1) {
        const float na = __shfl_up_sync(0xffffffffu, a, o);
        const float nb = __shfl_up_sync(0xffffffffu, b, o);
        if (lane >= o) { a += na; b += nb; }
    }
}

__inline__ __device__ float4 f4add(float4 a, float4 b) {
    return make_float4(a.x + b.x, a.y + b.y, a.z + b.z, a.w + b.w);
}
__inline__ __device__ float4 f4sub(float4 a, float4 b) {
    return make_float4(a.x - b.x, a.y - b.y, a.z - b.z, a.w - b.w);
}

template <bool INTERIOR>
__device__ __forceinline__ void run_strip(
    const float4* __restrict__ t, const float4* __restrict__ p,
    int r0, int w, int lane, int wid,
    float4 (*sP)[2][136], float2 (*s_warp)[4],
    float& acc0, float& acc1, float& acc2, float& acc3)
{
    const float4 zero4 = make_float4(0.f, 0.f, 0.f, 0.f);
    const float invf = 1.0f / (KS * KS);

    // ---- preamble vertical window: rows [r0-15, r0+14] (clamped) ----
    float4 sA = zero4, sB = zero4;
    if (INTERIOR) {
        const float4* tb = t + (r0 - PAD) * C4 + w;
        #pragma unroll
        for (int h = 0; h < 2 * PAD; h += 2) {
            sA = f4add(sA, tb[h * C4]);
            sB = f4add(sB, tb[(h + 1) * C4]);
        }
    } else {
        int hlo = r0 - PAD; if (hlo < 0) hlo = 0;
        int hhi = r0 + PAD; if (hhi > H) hhi = H;
        int h = hlo;
        for (; h + 1 < hhi; h += 2) {
            sA = f4add(sA, t[h * C4 + w]);
            sB = f4add(sB, t[(h + 1) * C4 + w]);
        }
        if (h < hhi) sA = f4add(sA, t[h * C4 + w]);
    }
    float4 sum4 = f4add(sA, sB);

    // cursors at row r (start r0), column w
    const float4* tc = t + r0 * C4 + w;
    const float4* pc = p + r0 * C4 + w;

    for (int g = 0; g < ROUNDS; ++g) {
        const int r   = r0 + 2 * g;
        const int buf = g & 1;

        float4 a0, a1, s0, s1;
        if (INTERIOR) {
            a0 = tc[15 * C4];
            a1 = tc[16 * C4];
            s0 = tc[-15 * C4];
            s1 = tc[-14 * C4];
        } else {
            a0 = (r + PAD < H)      ? tc[15 * C4]  : zero4;
            a1 = (r + 1 + PAD < H)  ? tc[16 * C4]  : zero4;
            s0 = (r - PAD >= 0)     ? tc[-15 * C4] : zero4;
            s1 = (r + 1 - PAD >= 0) ? tc[-14 * C4] : zero4;
        }

        sum4 = f4add(sum4, a0);
        const float4 vs0 = sum4;
        sum4 = f4sub(sum4, s0);
        sum4 = f4add(sum4, a1);
        const float4 vs1 = sum4;
        sum4 = f4sub(sum4, s1);

        // thread-local prefixes
        const float q0a = vs0.x, q1a = q0a + vs0.y, q2a = q1a + vs0.z, q3a = q2a + vs0.w;
        const float q0b = vs1.x, q1b = q0b + vs1.y, q2b = q1b + vs1.z, q3b = q2b + vs1.w;

        float ia = q3a, ib = q3b;
        warp_iscan2(ia, ib, lane);
        const float exa = ia - q3a;
        const float exb = ib - q3b;
        if (lane == 31) s_warp[buf][wid] = make_float2(ia, ib);
        __syncthreads();

        // tg/x loads issued here: latency hidden by base computation + stores
        const float4 tg0 = tc[0];
        const float4 tg1 = tc[C4];
        const float4 x0  = pc[0];
        const float4 x1  = pc[C4];

        const float2 W0 = s_warp[buf][0];
        const float2 W1 = s_warp[buf][1];
        const float2 W2 = s_warp[buf][2];
        const float2 W3 = s_warp[buf][3];

        const float offa = (wid > 0 ? W0.x : 0.f) + (wid > 1 ? W1.x : 0.f) + (wid > 2 ? W2.x : 0.f);
        const float offb = (wid > 0 ? W0.y : 0.f) + (wid > 1 ? W1.y : 0.f) + (wid > 2 ? W2.y : 0.f);
        const float basea = offa + exa;
        const float baseb = offb + exb;

        sP[buf][0][w + 4] = make_float4(basea + q0a, basea + q1a, basea + q2a, basea + q3a);
        sP[buf][1][w + 4] = make_float4(baseb + q0b, baseb + q1b, baseb + q2b, baseb + q3b);
        if (w < 4) {
            const float tota = W0.x + W1.x + W2.x + W3.x;
            const float totb = W0.y + W1.y + W2.y + W3.y;
            sP[buf][0][132 + w] = make_float4(tota, tota, tota, tota);
            sP[buf][1][132 + w] = make_float4(totb, totb, totb, totb);
        }
        __syncthreads();

        #pragma unroll
        for (int j = 0; j < 2; ++j) {
            const float4 lo = sP[buf][j][w];
            const float4 A  = sP[buf][j][w + 7];
            const float4 Bv = sP[buf][j][w + 8];
            const float4 tg = j ? tg1 : tg0;
            const float4 xq = j ? x1 : x0;

            const float hi[4]  = {A.w, Bv.x, Bv.y, Bv.z};
            const float lov[4] = {lo.x, lo.y, lo.z, lo.w};
            const float tgv[4] = {tg.x, tg.y, tg.z, tg.w};
            const float xv[4]  = {xq.x, xq.y, xq.z, xq.w};

            #pragma unroll
            for (int k = 0; k < 4; ++k) {
                const float box  = (hi[k] - lov[k]) * invf;
                const float weit = fmaf(5.f, fabsf(box - tgv[k]), 1.f);

                // exact: log1p(e^{-x}) + x = max(x,0) + log1p(e^{-|x|})
                const float u   = __expf(-xv[k]);
                const float v   = 1.f + u;
                const float lg  = __logf(v);
                const float bce = fmaf(-xv[k], tgv[k], lg + xv[k]);
                const float pr  = __fdividef(1.f, v);   // sigmoid(x)

                acc0 += weit;
                acc1 = fmaf(weit, bce, acc1);
                acc2 = fmaf(pr * tgv[k], weit, acc2);
                acc3 = fmaf(pr + tgv[k], weit, acc3);
            }
        }

        tc += 2 * C4;
        pc += 2 * C4;
    }
}

__global__ void __launch_bounds__(128, 9)
fused_loss_kernel(const float4* __restrict__ pred,
                  const float4* __restrict__ target,
                  float* __restrict__ out) {
    const int strip = blockIdx.x;
    const int b     = blockIdx.y;
    const int w     = threadIdx.x;
    const int lane  = w & 31;
    const int wid   = w >> 5;
    const int r0    = strip * ROWS;

    const float4* t = target + b * IMG4;
    const float4* p = pred   + b * IMG4;

    __shared__ float4 sP[2][2][136];
    __shared__ float2 s_warp[2][4];
    __shared__ float  s_red[4][4];

    if (w < 16) sP[(w >> 3) & 1][(w >> 2) & 1][w & 3] = make_float4(0.f, 0.f, 0.f, 0.f);

    float acc0 = 0.f, acc1 = 0.f, acc2 = 0.f, acc3 = 0.f;

    if (strip >= 1 && strip <= STRIPS - 2) {
        run_strip<true>(t, p, r0, w, lane, wid, sP, s_warp, acc0, acc1, acc2, acc3);
    } else {
        run_strip<false>(t, p, r0, w, lane, wid, sP, s_warp, acc0, acc1, acc2, acc3);
    }

    // ---- block reduction (4 warps) ----
    float vals[4] = {acc0, acc1, acc2, acc3};
    #pragma unroll
    for (int k = 0; k < 4; ++k) {
        const float v = warp_reduce(vals[k]);
        if (lane == 0) s_red[k][wid] = v;
    }
    __syncthreads();

    if (wid == 0) {
        float v[4];
        #pragma unroll
        for (int k = 0; k < 4; ++k) {
            float vv = (lane < 4) ? s_red[k][lane] : 0.f;
            #pragma unroll
            for (int o = 2; o > 0; o >>= 1) vv += __shfl_down_sync(0xffffffffu, vv, o);
            v[k] = vv;
        }
        if (lane == 0) {
            #pragma unroll
            for (int k = 0; k < 4; ++k)
                g_part[(b * STRIPS + strip) * 4 + k] = v[k];
            __threadfence();
        }
        __syncwarp();

        unsigned int ticket = 0;
        if (lane == 0) ticket = atomicAdd(&g_ctr, 1u);
        ticket = __shfl_sync(0xffffffffu, ticket, 0);
        if (ticket == NBLOCKS - 1) {
            float wsum = 0.f, wbce_n = 0.f, inter = 0.f, uni = 0.f;
            #pragma unroll 4
            for (int s = 0; s < STRIPS; ++s) {
                const float* pp = &g_part[(lane * STRIPS + s) * 4];
                wsum   += pp[0];
                wbce_n += pp[1];
                inter  += pp[2];
                uni    += pp[3];
            }
            const float wbce = wbce_n / wsum;
            const float wiou = 1.0f - (inter + 1.0f) / (uni - inter + 1.0f);
            float loss = warp_reduce(wbce + wiou);
            if (lane == 0) {
                out[0] = loss * (1.0f / B);
                g_ctr = 0;
            }
        }
    }
}

extern "C" void kernel_launch(void* const* d_in, const int* in_sizes, int n_in,
                              void* d_out, int out_size) {
    const float4* pred   = (const float4*)d_in[0];
    const float4* target = (const float4*)d_in[1];
    float* out = (float*)d_out;

    dim3 grid(STRIPS, B);
    fused_loss_kernel<<<grid, 128>>>(pred, target, out);
}